// round 12
// baseline (speedup 1.0000x reference)
#include <cuda_runtime.h>
#include <cuda_bf16.h>
#include <cstdint>
#include <cstddef>

// RNN-T beam search. B=8, T=128, H=1024, V=4096, K=5 (M = 40 hyps).
// Persistent kernel (2 CTAs/SM), FFMA2 GEMMs, cross-stage weight prefetch,
// topk on idle CTAs with flag sync (5 grid barriers + 1 flag per step).

#define HH   1024
#define VV   4096
#define BB   8
#define KBM  5
#define MM   40
#define TT   128
#define GRID_ALL 296
#define TKBASE 288
#define NEGF -3.0e38f

typedef unsigned long long u64;

// ----------------------------- device state --------------------------------
__device__ __align__(16) float g_tnproj[BB * TT * HH];
__device__ __align__(16) float g_WcatT[2048 * 4096];       // [k][n'] gate-permuted
__device__ __align__(16) float g_blstm_p[4096];            // permuted bias [4u+g]
__device__ __align__(16) float g_bufA[16 * MM * VV];       // gates/out partials
__device__ __align__(16) float g_bufB[32 * MM * HH];       // pn partials
__device__ __align__(16) float g_h[2][MM * HH];
__device__ __align__(16) float g_c[2][MM * HH];
__device__ __align__(16) float g_hnew[MM * HH];
__device__ __align__(16) float g_cnew[MM * HH];
__device__ __align__(16) float g_joint[MM * HH];
__device__ float g_rmax[MM * 128];
__device__ float g_rsum[MM * 128];
__device__ float g_t5v[MM * 640];
__device__ int   g_t5i[MM * 640];
__device__ float g_scores[2][MM];
__device__ int   g_tokens[2][MM];
__device__ int   g_lens[2][MM];
__device__ int   g_preds[2][MM * TT];
__device__ unsigned int g_barcnt;
__device__ unsigned int g_tkflag;

__device__ __forceinline__ float sigm(float x) { return 1.0f / (1.0f + expf(-x)); }

// ----------------------------- packed f32x2 ---------------------------------
__device__ __forceinline__ u64 pk2(float a) {
    u64 r;
    asm("mov.b64 %0, {%1, %1};" : "=l"(r) : "f"(a));
    return r;
}
__device__ __forceinline__ void fma2(u64& d, u64 a, u64 b) {
    asm("fma.rn.f32x2 %0, %1, %2, %0;" : "+l"(d) : "l"(a), "l"(b));
}

// ----------------------------- cp.async helpers -----------------------------
__device__ __forceinline__ void cpa16(void* s, const void* g) {
    uint32_t sa = (uint32_t)__cvta_generic_to_shared(s);
    asm volatile("cp.async.cg.shared.global [%0], [%1], 16;" :: "r"(sa), "l"(g));
}
#define CPA_COMMIT()  asm volatile("cp.async.commit_group;" ::: "memory")
#define CPA_WAIT(N)   asm volatile("cp.async.wait_group %0;" :: "n"(N) : "memory")

// ---------------------- sync primitives ------------------------------------
__device__ __forceinline__ void gbar(unsigned int& ph) {
    __syncthreads();
    ph++;
    if (threadIdx.x == 0) {
        asm volatile("red.release.gpu.add.u32 [%0], %1;"
                     :: "l"(&g_barcnt), "r"(1u) : "memory");
        unsigned int target = ph * (unsigned int)GRID_ALL;
        unsigned int v;
        while (true) {
            asm volatile("ld.acquire.gpu.u32 %0, [%1];"
                         : "=r"(v) : "l"(&g_barcnt) : "memory");
            if (v >= target) break;
            __nanosleep(32);
        }
    }
    __syncthreads();
}

__device__ __forceinline__ void flag_wait(unsigned int target) {
    unsigned int v;
    while (true) {
        asm volatile("ld.acquire.gpu.u32 %0, [%1];"
                     : "=r"(v) : "l"(&g_tkflag) : "memory");
        if (v >= target) break;
        __nanosleep(32);
    }
}

// ----------------------------- init ----------------------------------------
__global__ void init_state(const float* __restrict__ b_lstm) {
    int idx = blockIdx.x * 256 + threadIdx.x;
    if (idx < MM * HH) { g_h[0][idx] = 0.0f; g_c[0][idx] = 0.0f; }
    if (idx < MM) {
        g_scores[0][idx] = (idx % KBM == 0) ? 0.0f : -1e9f;
        g_tokens[0][idx] = 0;
        g_lens[0][idx]   = 0;
    }
    if (idx < MM * TT) g_preds[0][idx] = 0;
    if (idx < 4096) g_blstm_p[idx] = b_lstm[(idx & 3) * 1024 + (idx >> 2)];
    if (idx == 0) { g_barcnt = 0u; g_tkflag = 0u; }
}

// --------------------- weight transpose + gate permute ----------------------
__global__ void permute_w(const float* __restrict__ Wih,
                          const float* __restrict__ Whh) {
    __shared__ float tile[32][33];
    int x = threadIdx.x, y0 = threadIdx.y;
    int kt = blockIdx.x * 32, nt = blockIdx.y * 32;
#pragma unroll
    for (int yy = 0; yy < 32; yy += 8) {
        int np = nt + y0 + yy;
        int row = (np & 3) * 1024 + (np >> 2);
        int k = kt + x;
        float v = (k < 1024) ? Wih[(size_t)row * 1024 + k]
                             : Whh[(size_t)row * 1024 + k - 1024];
        tile[y0 + yy][x] = v;
    }
    __syncthreads();
#pragma unroll
    for (int yy = 0; yy < 32; yy += 8) {
        int k = kt + y0 + yy;
        int np = nt + x;
        g_WcatT[(size_t)k * 4096 + np] = tile[x][y0 + yy];
    }
}

// ----------------------------- tn_proj GEMM --------------------------------
__global__ __launch_bounds__(256) void tnproj_gemm(const float* __restrict__ A,
                                                   const float* __restrict__ Bm) {
    __shared__ float As[16][65];
    __shared__ float Bs[16][64];
    int tid = threadIdx.x;
    int tx = tid & 15, ty = tid >> 4;
    int m0 = blockIdx.y * 64, n0 = blockIdx.x * 64;
    float acc[4][4];
#pragma unroll
    for (int i = 0; i < 4; i++)
#pragma unroll
        for (int j = 0; j < 4; j++) acc[i][j] = 0.0f;
    for (int kk = 0; kk < 1024; kk += 16) {
        {
            int mm = tid >> 2;
            int kq = (tid & 3) * 4;
            float4 v = *(const float4*)&A[(size_t)(m0 + mm) * 1024 + kk + kq];
            As[kq + 0][mm] = v.x; As[kq + 1][mm] = v.y;
            As[kq + 2][mm] = v.z; As[kq + 3][mm] = v.w;
        }
#pragma unroll
        for (int r = 0; r < 4; r++) {
            int idx = tid + r * 256;
            int k = idx >> 6, n = idx & 63;
            Bs[k][n] = Bm[(size_t)(kk + k) * 1024 + n0 + n];
        }
        __syncthreads();
#pragma unroll
        for (int k = 0; k < 16; k++) {
            float a[4], b[4];
#pragma unroll
            for (int i = 0; i < 4; i++) a[i] = As[k][ty + 16 * i];
#pragma unroll
            for (int j = 0; j < 4; j++) b[j] = Bs[k][tx + 16 * j];
#pragma unroll
            for (int i = 0; i < 4; i++)
#pragma unroll
                for (int j = 0; j < 4; j++) acc[i][j] += a[i] * b[j];
        }
        __syncthreads();
    }
#pragma unroll
    for (int i = 0; i < 4; i++)
#pragma unroll
        for (int j = 0; j < 4; j++)
            g_tnproj[(size_t)(m0 + ty + 16 * i) * 1024 + n0 + tx + 16 * j] = acc[i][j];
}

// =========================== persistent stages ==============================
struct Smem {
    float As[2][MM][32];      // pn views As[0] as [20][128] not used here; R7 layout
    float Bs[2][32][256];
    int   tok[MM];
};

// FFMA2 inner product, tile 40x256.
__device__ __forceinline__ void mm_compute2(const float (*As)[32], const float (*Bs)[256],
                                            u64 acc[5][4], int nn2, int mg) {
#pragma unroll 4
    for (int kk = 0; kk < 32; kk++) {
        u64 b[4];
#pragma unroll
        for (int j = 0; j < 4; j++) b[j] = *(const u64*)&Bs[kk][nn2 + 64 * j];
#pragma unroll
        for (int i = 0; i < 5; i++) {
            u64 a2 = pk2(As[mg * 5 + i][kk]);
#pragma unroll
            for (int j = 0; j < 4; j++) fma2(acc[i][j], a2, b[j]);
        }
    }
}

// ---- gates: 16 col-blocks(256) x 16 k-splits(128) = 256 CTAs, 4 chunks ----
// B(0) prefetched pre-barrier (during stats of t-1).
__device__ void gates_prefetch(Smem* sm, int blk) {
    if (blk >= 256) return;
    int tid = threadIdx.x;
    int cb = blk & 15, sp = blk >> 4;
    int n0 = cb * 256, kg = sp * 128;
#pragma unroll
    for (int r = 0; r < 8; r++) {
        int idx = tid + r * 256;
        int kk = idx >> 6, nq = (idx & 63) * 4;
        cpa16(&sm->Bs[0][kk][nq], &g_WcatT[(size_t)(kg + kk) * 4096 + n0 + nq]);
    }
    CPA_COMMIT();
}

__device__ void gates_stage(Smem* sm, int blk, int cur, int t,
                            const float* __restrict__ E) {
    int tid = threadIdx.x;
    int cb = blk & 15, sp = blk >> 4;
    int n0 = cb * 256, kb0 = sp * 128;
    // wait for topk(t-1) results (tokens, h/c state)
    if (tid == 0 && t > 0) flag_wait(8u * (unsigned)t);
    __syncthreads();
    if (tid < MM) sm->tok[tid] = g_tokens[cur][tid];
    __syncthreads();

    auto stageA = [&](int c) {
        int kg = kb0 + c * 32;
        int buf = c & 1;
#pragma unroll
        for (int r = 0; r < 2; r++) {
            int idx = tid + r * 256;
            if (idx < 320) {
                int m = idx >> 3, q = (idx & 7) * 4;
                const float* src = (kg < 1024)
                    ? &E[(size_t)sm->tok[m] * HH + kg + q]
                    : &g_h[cur][m * HH + (kg - 1024) + q];
                cpa16(&sm->As[buf][m][q], src);
            }
        }
    };
    auto stageB = [&](int c) {
        int kg = kb0 + c * 32;
        int buf = c & 1;
#pragma unroll
        for (int r = 0; r < 8; r++) {
            int idx = tid + r * 256;
            int kk = idx >> 6, nq = (idx & 63) * 4;
            cpa16(&sm->Bs[buf][kk][nq], &g_WcatT[(size_t)(kg + kk) * 4096 + n0 + nq]);
        }
    };

    u64 acc[5][4];
#pragma unroll
    for (int i = 0; i < 5; i++)
#pragma unroll
        for (int j = 0; j < 4; j++) acc[i][j] = 0ull;
    int nn2 = (tid & 31) * 2, mg = tid >> 5;

    stageA(0); CPA_COMMIT();              // pending: B0(prefetched), A0
    for (int c = 0; c < 4; c++) {
        if (c + 1 < 4) { stageA(c + 1); stageB(c + 1); CPA_COMMIT(); CPA_WAIT(1); }
        else           { CPA_WAIT(0); }
        __syncthreads();
        mm_compute2(sm->As[c & 1], sm->Bs[c & 1], acc, nn2, mg);
        __syncthreads();
    }
    float* p = g_bufA + (size_t)sp * MM * VV;
#pragma unroll
    for (int i = 0; i < 5; i++)
#pragma unroll
        for (int j = 0; j < 4; j++)
            *(u64*)&p[(mg * 5 + i) * VV + n0 + 64 * j + nn2] = acc[i][j];
}

// ---- pn: 4 col-blocks(256) x 32 k-splits(32) = 128 CTAs, LSTM prologue ----
// B prefetched pre-barrier (end of gates region).
__device__ void pn_prefetch(Smem* sm, int blk, const float* __restrict__ Wpn) {
    if (blk >= 128) return;
    int tid = threadIdx.x;
    int cb = blk & 3, s = blk >> 2;
    int n0 = cb * 256, kl = s * 32;
#pragma unroll
    for (int r = 0; r < 8; r++) {
        int idx = tid + r * 256;
        int kk = idx >> 6, nq = (idx & 63) * 4;
        cpa16(&sm->Bs[0][kk][nq], &Wpn[(size_t)(kl + kk) * HH + n0 + nq]);
    }
    CPA_COMMIT();
}

__device__ void pn_stage(Smem* sm, int blk, int cur) {
    int tid = threadIdx.x;
    int cb = blk & 3, s = blk >> 2;
    int n0 = cb * 256, kl = s * 32;

    // LSTM prologue: hnew for (m, u=kl..kl+31) -> As[0][kk... row m][kk]
#pragma unroll
    for (int r = 0; r < 5; r++) {
        int idx = tid + r * 256;
        int m = idx >> 5, kk = idx & 31;
        int u = kl + kk;
        float4 s4 = make_float4(0.f, 0.f, 0.f, 0.f);
#pragma unroll
        for (int sp = 0; sp < 16; sp++) {
            float4 q = *(const float4*)&g_bufA[(size_t)sp * MM * VV + m * VV + 4 * u];
            s4.x += q.x; s4.y += q.y; s4.z += q.z; s4.w += q.w;
        }
        float4 bb = *(const float4*)&g_blstm_p[4 * u];
        float gi = s4.x + bb.x, gf = s4.y + bb.y, gg = s4.z + bb.z, go = s4.w + bb.w;
        float co = g_c[cur][m * HH + u];
        float cn = sigm(gf) * co + sigm(gi) * tanhf(gg);
        float hn = sigm(go) * tanhf(cn);
        sm->As[0][m][kk] = hn;
        if (cb == 0) { g_hnew[m * HH + u] = hn; g_cnew[m * HH + u] = cn; }
    }
    CPA_WAIT(0);
    __syncthreads();

    u64 acc[5][4];
#pragma unroll
    for (int i = 0; i < 5; i++)
#pragma unroll
        for (int j = 0; j < 4; j++) acc[i][j] = 0ull;
    int nn2 = (tid & 31) * 2, mg = tid >> 5;
    mm_compute2(sm->As[0], sm->Bs[0], acc, nn2, mg);
    __syncthreads();

    float* p = g_bufB + (size_t)s * MM * HH;
#pragma unroll
    for (int i = 0; i < 5; i++)
#pragma unroll
        for (int j = 0; j < 4; j++)
            *(u64*)&p[(mg * 5 + i) * HH + n0 + 64 * j + nn2] = acc[i][j];
}

// ---- joint: all CTAs, reduce 32 pn partials + bias + tnproj -> tanh -------
__device__ void joint_stage(const float* __restrict__ b_joint, int t, int blk) {
    for (int e = blk * 256 + threadIdx.x; e < MM * HH; e += GRID_ALL * 256) {
        int m = e >> 10, j = e & 1023;
        float v = b_joint[j];
#pragma unroll
        for (int s = 0; s < 32; s++) v += g_bufB[(size_t)s * MM * HH + e];
        int b = m / KBM;
        v += g_tnproj[((size_t)b * TT + t) * HH + j];
        g_joint[e] = tanhf(v);
    }
}

// ---- out: 16 col-blocks(256) x 16 k-splits(64) = 256 CTAs, 2 chunks -------
// B(0) prefetched at start of joint region (overlaps joint compute).
__device__ void out_prefetch(Smem* sm, int blk, const float* __restrict__ Wout) {
    if (blk >= 256) return;
    int tid = threadIdx.x;
    int cb = blk & 15, sp = blk >> 4;
    int n0 = cb * 256, kb0 = sp * 64;
#pragma unroll
    for (int r = 0; r < 8; r++) {
        int idx = tid + r * 256;
        int kk = idx >> 6, nq = (idx & 63) * 4;
        cpa16(&sm->Bs[0][kk][nq], &Wout[(size_t)(kb0 + kk) * VV + n0 + nq]);
    }
    CPA_COMMIT();
}

__device__ void out_stage(Smem* sm, int blk, const float* __restrict__ Wout) {
    int tid = threadIdx.x;
    int cb = blk & 15, sp = blk >> 4;
    int n0 = cb * 256, kb0 = sp * 64;

    auto stageA = [&](int c) {
        int kg = kb0 + c * 32;
        int buf = c & 1;
#pragma unroll
        for (int r = 0; r < 2; r++) {
            int idx = tid + r * 256;
            if (idx < 320) {
                int m = idx >> 3, q = (idx & 7) * 4;
                cpa16(&sm->As[buf][m][q], &g_joint[m * HH + kg + q]);
            }
        }
    };
    auto stageB1 = [&]() {
        int kg = kb0 + 32;
#pragma unroll
        for (int r = 0; r < 8; r++) {
            int idx = tid + r * 256;
            int kk = idx >> 6, nq = (idx & 63) * 4;
            cpa16(&sm->Bs[1][kk][nq], &Wout[(size_t)(kg + kk) * VV + n0 + nq]);
        }
    };

    u64 acc[5][4];
#pragma unroll
    for (int i = 0; i < 5; i++)
#pragma unroll
        for (int j = 0; j < 4; j++) acc[i][j] = 0ull;
    int nn2 = (tid & 31) * 2, mg = tid >> 5;

    stageA(0); CPA_COMMIT();              // pending: B0(prefetched), A0
    stageA(1); stageB1(); CPA_COMMIT();   // pending: +1
    CPA_WAIT(1);
    __syncthreads();
    mm_compute2(sm->As[0], sm->Bs[0], acc, nn2, mg);
    __syncthreads();
    CPA_WAIT(0);
    __syncthreads();
    mm_compute2(sm->As[1], sm->Bs[1], acc, nn2, mg);
    __syncthreads();

    float* p = g_bufA + (size_t)sp * MM * VV;
#pragma unroll
    for (int i = 0; i < 5; i++)
#pragma unroll
        for (int j = 0; j < 4; j++)
            *(u64*)&p[(mg * 5 + i) * VV + n0 + 64 * j + nn2] = acc[i][j];
}

// ---- stats: all CTAs, 5120 (row, 32-col slice) tasks, reduce 16 partials --
__device__ void stats_stage(int blk, const float* __restrict__ bout) {
    int warp = threadIdx.x >> 5, lane = threadIdx.x & 31;
    unsigned full = 0xffffffffu;
    for (int tk = blk * 8 + warp; tk < MM * 128; tk += GRID_ALL * 8) {
        int row = tk >> 7, sl = tk & 127;
        int col = sl * 32 + lane;
        float v = bout[col];
#pragma unroll
        for (int sp = 0; sp < 16; sp++)
            v += g_bufA[(size_t)sp * MM * VV + (size_t)row * VV + col];
        float mx = v;
#pragma unroll
        for (int off = 16; off > 0; off >>= 1)
            mx = fmaxf(mx, __shfl_xor_sync(full, mx, off));
        float se = expf(v - mx);
#pragma unroll
        for (int off = 16; off > 0; off >>= 1)
            se += __shfl_xor_sync(full, se, off);
        bool chosen = false;
        for (int j = 0; j < KBM; j++) {
            float cv = chosen ? NEGF : v;
            int ci = col;
#pragma unroll
            for (int off = 16; off > 0; off >>= 1) {
                float ov = __shfl_xor_sync(full, cv, off);
                int   oi = __shfl_xor_sync(full, ci, off);
                if (ov > cv || (ov == cv && oi < ci)) { cv = ov; ci = oi; }
            }
            if (lane == 0) {
                g_t5v[row * 640 + sl * 5 + j] = cv;
                g_t5i[row * 640 + sl * 5 + j] = ci;
            }
            if (col == ci) chosen = true;
        }
        if (lane == 0) { g_rmax[row * 128 + sl] = mx; g_rsum[row * 128 + sl] = se; }
    }
}

// ---- topk merge + state update: CTAs TKBASE..TKBASE+7 (idle in GEMMs) -----
__device__ void topk_stage(int b, int cur) {
    int tid = threadIdx.x;
    int nxt = cur ^ 1;
    int warp = tid >> 5, lane = tid & 31;
    unsigned full = 0xffffffffu;
    __shared__ float t_rv[25];
    __shared__ int   t_ri[25];
    __shared__ float t_fv[KBM];
    __shared__ int   t_fi[KBM];
    __shared__ int   t_par[KBM], t_tok[KBM], t_blk2[KBM], t_plen[KBM];

    if (warp < KBM) {
        int row = b * KBM + warp;
        float rm[4], rs[4];
#pragma unroll
        for (int q = 0; q < 4; q++) {
            rm[q] = g_rmax[row * 128 + lane * 4 + q];
            rs[q] = g_rsum[row * 128 + lane * 4 + q];
        }
        float M = fmaxf(fmaxf(rm[0], rm[1]), fmaxf(rm[2], rm[3]));
#pragma unroll
        for (int off = 16; off > 0; off >>= 1)
            M = fmaxf(M, __shfl_xor_sync(full, M, off));
        float S = 0.f;
#pragma unroll
        for (int q = 0; q < 4; q++) S += rs[q] * expf(rm[q] - M);
#pragma unroll
        for (int off = 16; off > 0; off >>= 1)
            S += __shfl_xor_sync(full, S, off);
        float lse = M + logf(S);
        float sc = g_scores[cur][row];
        int selg[KBM]; float selv[KBM];
        for (int j = 0; j < KBM; j++) {
            float bv = NEGF; int bi = 0x7fffffff;
            for (int q = 0; q < 20; q++) {
                int c = lane * 20 + q;
                int gidx = warp * 4096 + g_t5i[row * 640 + c];
                bool skip = false;
                for (int p = 0; p < j; p++) if (gidx == selg[p]) skip = true;
                if (skip) continue;
                float adj = sc + g_t5v[row * 640 + c] - lse;
                if (adj > bv || (adj == bv && gidx < bi)) { bv = adj; bi = gidx; }
            }
#pragma unroll
            for (int off = 16; off > 0; off >>= 1) {
                float ov = __shfl_xor_sync(full, bv, off);
                int   oi = __shfl_xor_sync(full, bi, off);
                if (ov > bv || (ov == bv && oi < bi)) { bv = ov; bi = oi; }
            }
            selg[j] = bi; selv[j] = bv;
        }
        if (lane == 0) {
#pragma unroll
            for (int j = 0; j < KBM; j++) {
                t_rv[warp * KBM + j] = selv[j];
                t_ri[warp * KBM + j] = selg[j];
            }
        }
    }
    __syncthreads();
    if (warp == 0) {
        float v  = (lane < 25) ? t_rv[lane] : NEGF;
        int   gi = (lane < 25) ? t_ri[lane] : 0x7fffffff;
        bool chosen = false;
        for (int j = 0; j < KBM; j++) {
            float cv = chosen ? NEGF : v;
            int ci = gi;
#pragma unroll
            for (int off = 16; off > 0; off >>= 1) {
                float ov = __shfl_xor_sync(full, cv, off);
                int   oi = __shfl_xor_sync(full, ci, off);
                if (ov > cv || (ov == cv && oi < ci)) { cv = ov; ci = oi; }
            }
            if (lane == 0) { t_fv[j] = cv; t_fi[j] = ci; }
            if (gi == ci) chosen = true;
        }
    }
    __syncthreads();
    if (tid < KBM) {
        int idx = t_fi[tid];
        int par = idx >> 12, tok = idx & 4095;
        int blank = (tok == 0);
        int p = b * KBM + par, mn = b * KBM + tid;
        t_par[tid] = par; t_tok[tid] = tok; t_blk2[tid] = blank;
        int pl = g_lens[cur][p];
        t_plen[tid] = pl;
        g_scores[nxt][mn] = t_fv[tid];
        g_lens[nxt][mn]   = pl + (blank ? 0 : 1);
        g_tokens[nxt][mn] = blank ? g_tokens[cur][p] : tok;
    }
    __syncthreads();
    for (int j = 0; j < KBM; j++) {
        int p = b * KBM + t_par[j], mn = b * KBM + j;
        bool blank = (t_blk2[j] != 0);
        const float* hs = blank ? &g_h[cur][p * HH] : &g_hnew[p * HH];
        const float* cs = blank ? &g_c[cur][p * HH] : &g_cnew[p * HH];
        for (int i = tid; i < HH; i += 256) {
            g_h[nxt][mn * HH + i] = hs[i];
            g_c[nxt][mn * HH + i] = cs[i];
        }
        for (int i = tid; i < TT; i += 256) {
            int v = g_preds[cur][p * TT + i];
            if (!blank && i == t_plen[j]) v = t_tok[j];
            g_preds[nxt][mn * TT + i] = v;
        }
    }
    __syncthreads();
    if (tid == 0) {
        asm volatile("red.release.gpu.add.u32 [%0], %1;"
                     :: "l"(&g_tkflag), "r"(1u) : "memory");
    }
}

// ----------------------------- finalize -------------------------------------
__device__ void finalize_stage(float* __restrict__ out) {
    int tid = threadIdx.x;
    __shared__ float s_norm[MM];
    __shared__ int   s_best[BB];
    if (tid == 0) flag_wait(8u * (unsigned)TT);
    __syncthreads();
    if (tid < MM)
        s_norm[tid] = g_scores[0][tid] / ((float)g_lens[0][tid] + 1.0f);
    __syncthreads();
    if (tid < BB) {
        float bv = NEGF; int bj = 0;
        for (int j = 0; j < KBM; j++) {
            float v = s_norm[tid * KBM + j];
            if (v > bv) { bv = v; bj = j; }
        }
        s_best[tid] = bj;
        out[BB * TT + tid] = (float)g_lens[0][tid * KBM + bj];
    }
    if (tid < MM) out[BB * TT + BB + 1 + tid] = s_norm[tid];
    __syncthreads();
    if (tid == 0) {
        float acc = 0.0f;
        for (int b2 = 0; b2 < BB; b2++) {
            float bv = NEGF;
            for (int j = 0; j < KBM; j++) bv = fmaxf(bv, s_norm[b2 * KBM + j]);
            acc += expf(bv);
        }
        out[BB * TT + BB] = acc / (float)BB;
    }
    for (int b2 = 0; b2 < BB; b2++) {
        int m = b2 * KBM + s_best[b2];
        for (int i = tid; i < TT; i += 256)
            out[b2 * TT + i] = (float)g_preds[0][m * TT + i];
    }
}

// ----------------------------- persistent kernel ----------------------------
__global__ __launch_bounds__(256, 2) void persist(const float* __restrict__ E,
                                                  const float* __restrict__ Wpn,
                                                  const float* __restrict__ b_joint,
                                                  const float* __restrict__ Wout,
                                                  const float* __restrict__ bout,
                                                  float* __restrict__ out) {
    __shared__ Smem sm;
    unsigned int ph = 0;
    int blk = blockIdx.x;
    gates_prefetch(&sm, blk);                      // B(0) for t=0
    for (int t = 0; t < TT; t++) {
        int cur = t & 1;
        if (blk < 256) gates_stage(&sm, blk, cur, t, E);
        pn_prefetch(&sm, blk, Wpn);
        gbar(ph);
        if (blk < 128) pn_stage(&sm, blk, cur);
        gbar(ph);
        out_prefetch(&sm, blk, Wout);              // overlaps joint compute
        joint_stage(b_joint, t, blk);
        gbar(ph);
        if (blk < 256) out_stage(&sm, blk, Wout);
        gbar(ph);
        stats_stage(blk, bout);
        gates_prefetch(&sm, blk);                  // B(0) for t+1
        gbar(ph);
        if (blk >= TKBASE) topk_stage(blk - TKBASE, cur);
        // no grid barrier: gates(t+1) acquires the topk flag
    }
    CPA_WAIT(0);
    if (blk == 0) finalize_stage(out);
}

// ----------------------------- launch ---------------------------------------
extern "C" void kernel_launch(void* const* d_in, const int* in_sizes, int n_in,
                              void* d_out, int out_size) {
    const float* tn      = (const float*)d_in[0];
    const float* E       = (const float*)d_in[1];
    const float* W_ih    = (const float*)d_in[2];
    const float* W_hh    = (const float*)d_in[3];
    const float* b_lstm  = (const float*)d_in[4];
    const float* W_tn    = (const float*)d_in[5];
    const float* W_pn    = (const float*)d_in[6];
    const float* b_joint = (const float*)d_in[7];
    const float* W_out   = (const float*)d_in[8];
    const float* b_out   = (const float*)d_in[9];
    float* out = (float*)d_out;

    init_state<<<160, 256>>>(b_lstm);
    permute_w<<<dim3(64, 128), dim3(32, 8)>>>(W_ih, W_hh);
    tnproj_gemm<<<dim3(16, 16), 256>>>(tn, W_tn);
    persist<<<GRID_ALL, 256>>>(E, W_pn, b_joint, W_out, b_out, out);
}

// round 13
// speedup vs baseline: 1.1225x; 1.1225x over previous
#include <cuda_runtime.h>
#include <cuda_bf16.h>
#include <cstdint>
#include <cstddef>

// RNN-T beam search. B=8, T=128, H=1024, V=4096, K=5 (M = 40 hyps).
// Persistent kernel (2 CTAs/SM), cp.async double-buffered split-K GEMMs,
// packed fma.rn.f32x2 inner loops. R7 structure + acq/rel barrier +
// vectorized topk gather.

#define HH   1024
#define VV   4096
#define BB   8
#define KBM  5
#define MM   40
#define TT   128
#define GRID_ALL 296
#define NEGF -3.0e38f

typedef unsigned long long u64;

// ----------------------------- device state --------------------------------
__device__ __align__(16) float g_tnproj[BB * TT * HH];
__device__ __align__(16) float g_WcatT[2048 * 4096];       // [k][n'] gate-permuted
__device__ __align__(16) float g_blstm_p[4096];            // permuted bias [4u+g]
__device__ __align__(16) float g_bufA[16 * MM * VV];       // gates/out partials
__device__ __align__(16) float g_bufB[32 * MM * HH];       // pn partials
__device__ __align__(16) float g_h[2][MM * HH];
__device__ __align__(16) float g_c[2][MM * HH];
__device__ __align__(16) float g_hnew[MM * HH];
__device__ __align__(16) float g_cnew[MM * HH];
__device__ __align__(16) float g_joint[MM * HH];
__device__ float g_rmax[MM * 128];
__device__ float g_rsum[MM * 128];
__device__ float g_t5v[MM * 640];
__device__ int   g_t5i[MM * 640];
__device__ float g_scores[2][MM];
__device__ int   g_tokens[2][MM];
__device__ int   g_lens[2][MM];
__device__ __align__(16) int g_preds[2][MM * TT];
__device__ unsigned int g_barcnt;

__device__ __forceinline__ float sigm(float x) { return 1.0f / (1.0f + expf(-x)); }

// ----------------------------- packed f32x2 ---------------------------------
__device__ __forceinline__ u64 pk2(float a) {
    u64 r;
    asm("mov.b64 %0, {%1, %1};" : "=l"(r) : "f"(a));
    return r;
}
__device__ __forceinline__ void fma2(u64& d, u64 a, u64 b) {
    asm("fma.rn.f32x2 %0, %1, %2, %0;" : "+l"(d) : "l"(a), "l"(b));
}

// ----------------------------- cp.async helpers -----------------------------
__device__ __forceinline__ void cpa16(void* s, const void* g) {
    uint32_t sa = (uint32_t)__cvta_generic_to_shared(s);
    asm volatile("cp.async.cg.shared.global [%0], [%1], 16;" :: "r"(sa), "l"(g));
}
#define CPA_COMMIT()  asm volatile("cp.async.commit_group;" ::: "memory")
#define CPA_WAIT(N)   asm volatile("cp.async.wait_group %0;" :: "n"(N) : "memory")

// ---------------------- grid barrier (acq/rel, monotonic) -------------------
__device__ __forceinline__ void gbar(unsigned int& ph) {
    __syncthreads();
    ph++;
    if (threadIdx.x == 0) {
        asm volatile("red.release.gpu.add.u32 [%0], %1;"
                     :: "l"(&g_barcnt), "r"(1u) : "memory");
        unsigned int target = ph * (unsigned int)GRID_ALL;
        unsigned int v;
        while (true) {
            asm volatile("ld.acquire.gpu.u32 %0, [%1];"
                         : "=r"(v) : "l"(&g_barcnt) : "memory");
            if (v >= target) break;
            __nanosleep(32);
        }
    }
    __syncthreads();
}

// ----------------------------- init ----------------------------------------
__global__ void init_state(const float* __restrict__ b_lstm) {
    int idx = blockIdx.x * 256 + threadIdx.x;
    if (idx < MM * HH) { g_h[0][idx] = 0.0f; g_c[0][idx] = 0.0f; }
    if (idx < MM) {
        g_scores[0][idx] = (idx % KBM == 0) ? 0.0f : -1e9f;
        g_tokens[0][idx] = 0;
        g_lens[0][idx]   = 0;
    }
    if (idx < MM * TT) g_preds[0][idx] = 0;
    if (idx < 4096) g_blstm_p[idx] = b_lstm[(idx & 3) * 1024 + (idx >> 2)];
    if (idx == 0) g_barcnt = 0u;
}

// --------------------- weight transpose + gate permute ----------------------
__global__ void permute_w(const float* __restrict__ Wih,
                          const float* __restrict__ Whh) {
    __shared__ float tile[32][33];
    int x = threadIdx.x, y0 = threadIdx.y;
    int kt = blockIdx.x * 32, nt = blockIdx.y * 32;
#pragma unroll
    for (int yy = 0; yy < 32; yy += 8) {
        int np = nt + y0 + yy;
        int row = (np & 3) * 1024 + (np >> 2);
        int k = kt + x;
        float v = (k < 1024) ? Wih[(size_t)row * 1024 + k]
                             : Whh[(size_t)row * 1024 + k - 1024];
        tile[y0 + yy][x] = v;
    }
    __syncthreads();
#pragma unroll
    for (int yy = 0; yy < 32; yy += 8) {
        int k = kt + y0 + yy;
        int np = nt + x;
        g_WcatT[(size_t)k * 4096 + np] = tile[x][y0 + yy];
    }
}

// ----------------------------- tn_proj GEMM --------------------------------
__global__ __launch_bounds__(256) void tnproj_gemm(const float* __restrict__ A,
                                                   const float* __restrict__ Bm) {
    __shared__ float As[16][65];
    __shared__ float Bs[16][64];
    int tid = threadIdx.x;
    int tx = tid & 15, ty = tid >> 4;
    int m0 = blockIdx.y * 64, n0 = blockIdx.x * 64;
    float acc[4][4];
#pragma unroll
    for (int i = 0; i < 4; i++)
#pragma unroll
        for (int j = 0; j < 4; j++) acc[i][j] = 0.0f;
    for (int kk = 0; kk < 1024; kk += 16) {
        {
            int mm = tid >> 2;
            int kq = (tid & 3) * 4;
            float4 v = *(const float4*)&A[(size_t)(m0 + mm) * 1024 + kk + kq];
            As[kq + 0][mm] = v.x; As[kq + 1][mm] = v.y;
            As[kq + 2][mm] = v.z; As[kq + 3][mm] = v.w;
        }
#pragma unroll
        for (int r = 0; r < 4; r++) {
            int idx = tid + r * 256;
            int k = idx >> 6, n = idx & 63;
            Bs[k][n] = Bm[(size_t)(kk + k) * 1024 + n0 + n];
        }
        __syncthreads();
#pragma unroll
        for (int k = 0; k < 16; k++) {
            float a[4], b[4];
#pragma unroll
            for (int i = 0; i < 4; i++) a[i] = As[k][ty + 16 * i];
#pragma unroll
            for (int j = 0; j < 4; j++) b[j] = Bs[k][tx + 16 * j];
#pragma unroll
            for (int i = 0; i < 4; i++)
#pragma unroll
                for (int j = 0; j < 4; j++) acc[i][j] += a[i] * b[j];
        }
        __syncthreads();
    }
#pragma unroll
    for (int i = 0; i < 4; i++)
#pragma unroll
        for (int j = 0; j < 4; j++)
            g_tnproj[(size_t)(m0 + ty + 16 * i) * 1024 + n0 + tx + 16 * j] = acc[i][j];
}

// =========================== persistent stages ==============================
struct Smem {
    float As[2][MM][32];      // [m][k] chunk
    float Bs[2][32][256];     // [k][n] chunk
    int   tok[MM];
};

// FFMA2 inner product over one 32-k chunk; thread owns column pairs
// {nn2+64j, nn2+64j+1}, j=0..3, rows mg*5..mg*5+4.
__device__ __forceinline__ void mm_compute2(const float (*As)[32], const float (*Bs)[256],
                                            u64 acc[5][4], int nn2, int mg) {
#pragma unroll 4
    for (int kk = 0; kk < 32; kk++) {
        u64 b[4];
#pragma unroll
        for (int j = 0; j < 4; j++) b[j] = *(const u64*)&Bs[kk][nn2 + 64 * j];
#pragma unroll
        for (int i = 0; i < 5; i++) {
            u64 a2 = pk2(As[mg * 5 + i][kk]);
#pragma unroll
            for (int j = 0; j < 4; j++) fma2(acc[i][j], a2, b[j]);
        }
    }
}

// gates: 16 col-blocks(256) x 16 k-splits(128) = 256 CTAs, 4 chunks of 32.
__device__ void gates_stage(Smem* sm, int blk, int cur, const float* __restrict__ E) {
    int tid = threadIdx.x;
    int cb = blk & 15, sp = blk >> 4;
    int n0 = cb * 256, kb0 = sp * 128;
    if (tid < MM) sm->tok[tid] = g_tokens[cur][tid];
    __syncthreads();

    auto stage = [&](int c) {
        int kg = kb0 + c * 32;
        int buf = c & 1;
#pragma unroll
        for (int r = 0; r < 2; r++) {
            int idx = tid + r * 256;
            if (idx < 320) {
                int m = idx >> 3, q = (idx & 7) * 4;
                const float* src = (kg < 1024)
                    ? &E[(size_t)sm->tok[m] * HH + kg + q]
                    : &g_h[cur][m * HH + (kg - 1024) + q];
                cpa16(&sm->As[buf][m][q], src);
            }
        }
#pragma unroll
        for (int r = 0; r < 8; r++) {
            int idx = tid + r * 256;
            int kk = idx >> 6, nq = (idx & 63) * 4;
            cpa16(&sm->Bs[buf][kk][nq], &g_WcatT[(size_t)(kg + kk) * 4096 + n0 + nq]);
        }
        CPA_COMMIT();
    };

    u64 acc[5][4];
#pragma unroll
    for (int i = 0; i < 5; i++)
#pragma unroll
        for (int j = 0; j < 4; j++) acc[i][j] = 0ull;
    int nn2 = (tid & 31) * 2, mg = tid >> 5;

    stage(0);
    for (int c = 0; c < 4; c++) {
        if (c + 1 < 4) { stage(c + 1); CPA_WAIT(1); }
        else           { CPA_WAIT(0); }
        __syncthreads();
        mm_compute2(sm->As[c & 1], sm->Bs[c & 1], acc, nn2, mg);
        __syncthreads();
    }
    float* p = g_bufA + (size_t)sp * MM * VV;
#pragma unroll
    for (int i = 0; i < 5; i++)
#pragma unroll
        for (int j = 0; j < 4; j++)
            *(u64*)&p[(mg * 5 + i) * VV + n0 + 64 * j + nn2] = acc[i][j];
}

// pn: 4 col-blocks(256) x 32 k-splits(32) = 128 CTAs. LSTM-reduce prologue.
__device__ void pn_stage(Smem* sm, int blk, int cur, const float* __restrict__ Wpn) {
    int tid = threadIdx.x;
    int cb = blk & 3, s = blk >> 2;
    int n0 = cb * 256, kl = s * 32;

#pragma unroll
    for (int r = 0; r < 8; r++) {
        int idx = tid + r * 256;
        int kk = idx >> 6, nq = (idx & 63) * 4;
        cpa16(&sm->Bs[0][kk][nq], &Wpn[(size_t)(kl + kk) * HH + n0 + nq]);
    }
    CPA_COMMIT();

    // LSTM prologue: hnew for (m, u=kl..kl+31) -> As[0][m][kk]
#pragma unroll
    for (int r = 0; r < 5; r++) {
        int idx = tid + r * 256;
        int m = idx >> 5, kk = idx & 31;
        int u = kl + kk;
        float4 s4 = make_float4(0.f, 0.f, 0.f, 0.f);
#pragma unroll
        for (int sp2 = 0; sp2 < 16; sp2++) {
            float4 q = *(const float4*)&g_bufA[(size_t)sp2 * MM * VV + m * VV + 4 * u];
            s4.x += q.x; s4.y += q.y; s4.z += q.z; s4.w += q.w;
        }
        float4 bb = *(const float4*)&g_blstm_p[4 * u];
        float gi = s4.x + bb.x, gf = s4.y + bb.y, gg = s4.z + bb.z, go = s4.w + bb.w;
        float co = g_c[cur][m * HH + u];
        float cn = sigm(gf) * co + sigm(gi) * tanhf(gg);
        float hn = sigm(go) * tanhf(cn);
        sm->As[0][m][kk] = hn;
        if (cb == 0) { g_hnew[m * HH + u] = hn; g_cnew[m * HH + u] = cn; }
    }
    CPA_WAIT(0);
    __syncthreads();

    u64 acc[5][4];
#pragma unroll
    for (int i = 0; i < 5; i++)
#pragma unroll
        for (int j = 0; j < 4; j++) acc[i][j] = 0ull;
    int nn2 = (tid & 31) * 2, mg = tid >> 5;
    mm_compute2(sm->As[0], sm->Bs[0], acc, nn2, mg);
    __syncthreads();

    float* p = g_bufB + (size_t)s * MM * HH;
#pragma unroll
    for (int i = 0; i < 5; i++)
#pragma unroll
        for (int j = 0; j < 4; j++)
            *(u64*)&p[(mg * 5 + i) * HH + n0 + 64 * j + nn2] = acc[i][j];
}

// joint: all CTAs, reduce 32 pn partials + bias + tnproj -> tanh
__device__ void joint_stage(const float* __restrict__ b_joint, int t, int blk) {
    for (int e = blk * 256 + threadIdx.x; e < MM * HH; e += GRID_ALL * 256) {
        int m = e >> 10, j = e & 1023;
        float v = b_joint[j];
#pragma unroll
        for (int s = 0; s < 32; s++) v += g_bufB[(size_t)s * MM * HH + e];
        int b = m / KBM;
        v += g_tnproj[((size_t)b * TT + t) * HH + j];
        g_joint[e] = tanhf(v);
    }
}

// out: 16 col-blocks(256) x 16 k-splits(64) = 256 CTAs, 2 chunks of 32.
__device__ void out_stage(Smem* sm, int blk, const float* __restrict__ Wout) {
    int tid = threadIdx.x;
    int cb = blk & 15, sp = blk >> 4;
    int n0 = cb * 256, kb0 = sp * 64;

    auto stage = [&](int c) {
        int kg = kb0 + c * 32;
        int buf = c & 1;
#pragma unroll
        for (int r = 0; r < 2; r++) {
            int idx = tid + r * 256;
            if (idx < 320) {
                int m = idx >> 3, q = (idx & 7) * 4;
                cpa16(&sm->As[buf][m][q], &g_joint[m * HH + kg + q]);
            }
        }
#pragma unroll
        for (int r = 0; r < 8; r++) {
            int idx = tid + r * 256;
            int kk = idx >> 6, nq = (idx & 63) * 4;
            cpa16(&sm->Bs[buf][kk][nq], &Wout[(size_t)(kg + kk) * VV + n0 + nq]);
        }
        CPA_COMMIT();
    };

    u64 acc[5][4];
#pragma unroll
    for (int i = 0; i < 5; i++)
#pragma unroll
        for (int j = 0; j < 4; j++) acc[i][j] = 0ull;
    int nn2 = (tid & 31) * 2, mg = tid >> 5;

    stage(0);
    for (int c = 0; c < 2; c++) {
        if (c + 1 < 2) { stage(c + 1); CPA_WAIT(1); }
        else           { CPA_WAIT(0); }
        __syncthreads();
        mm_compute2(sm->As[c & 1], sm->Bs[c & 1], acc, nn2, mg);
        __syncthreads();
    }
    float* p = g_bufA + (size_t)sp * MM * VV;
#pragma unroll
    for (int i = 0; i < 5; i++)
#pragma unroll
        for (int j = 0; j < 4; j++)
            *(u64*)&p[(mg * 5 + i) * VV + n0 + 64 * j + nn2] = acc[i][j];
}

// stats: all CTAs. 5120 (row, 32-col slice) tasks.
__device__ void stats_stage(int blk, const float* __restrict__ bout) {
    int warp = threadIdx.x >> 5, lane = threadIdx.x & 31;
    unsigned full = 0xffffffffu;
    for (int tk = blk * 8 + warp; tk < MM * 128; tk += GRID_ALL * 8) {
        int row = tk >> 7, sl = tk & 127;
        int col = sl * 32 + lane;
        float v = bout[col];
#pragma unroll
        for (int sp = 0; sp < 16; sp++)
            v += g_bufA[(size_t)sp * MM * VV + (size_t)row * VV + col];
        float mx = v;
#pragma unroll
        for (int off = 16; off > 0; off >>= 1)
            mx = fmaxf(mx, __shfl_xor_sync(full, mx, off));
        float se = expf(v - mx);
#pragma unroll
        for (int off = 16; off > 0; off >>= 1)
            se += __shfl_xor_sync(full, se, off);
        bool chosen = false;
        for (int j = 0; j < KBM; j++) {
            float cv = chosen ? NEGF : v;
            int ci = col;
#pragma unroll
            for (int off = 16; off > 0; off >>= 1) {
                float ov = __shfl_xor_sync(full, cv, off);
                int   oi = __shfl_xor_sync(full, ci, off);
                if (ov > cv || (ov == cv && oi < ci)) { cv = ov; ci = oi; }
            }
            if (lane == 0) {
                g_t5v[row * 640 + sl * 5 + j] = cv;
                g_t5i[row * 640 + sl * 5 + j] = ci;
            }
            if (col == ci) chosen = true;
        }
        if (lane == 0) { g_rmax[row * 128 + sl] = mx; g_rsum[row * 128 + sl] = se; }
    }
}

// topk merge + state update: 8 CTAs (one per batch). Vectorized gathers.
__device__ void topk_stage(int b, int cur) {
    int tid = threadIdx.x;
    int nxt = cur ^ 1;
    int warp = tid >> 5, lane = tid & 31;
    unsigned full = 0xffffffffu;
    __shared__ float t_rv[25];
    __shared__ int   t_ri[25];
    __shared__ float t_fv[KBM];
    __shared__ int   t_fi[KBM];
    __shared__ int   t_par[KBM], t_tok[KBM], t_blk2[KBM], t_plen[KBM];

    if (warp < KBM) {
        int row = b * KBM + warp;
        float rm[4], rs[4];
#pragma unroll
        for (int q = 0; q < 4; q++) {
            rm[q] = g_rmax[row * 128 + lane * 4 + q];
            rs[q] = g_rsum[row * 128 + lane * 4 + q];
        }
        float M = fmaxf(fmaxf(rm[0], rm[1]), fmaxf(rm[2], rm[3]));
#pragma unroll
        for (int off = 16; off > 0; off >>= 1)
            M = fmaxf(M, __shfl_xor_sync(full, M, off));
        float S = 0.f;
#pragma unroll
        for (int q = 0; q < 4; q++) S += rs[q] * expf(rm[q] - M);
#pragma unroll
        for (int off = 16; off > 0; off >>= 1)
            S += __shfl_xor_sync(full, S, off);
        float lse = M + logf(S);
        float sc = g_scores[cur][row];
        int selg[KBM]; float selv[KBM];
        for (int j = 0; j < KBM; j++) {
            float bv = NEGF; int bi = 0x7fffffff;
            for (int q = 0; q < 20; q++) {
                int c = lane * 20 + q;
                int gidx = warp * 4096 + g_t5i[row * 640 + c];
                bool skip = false;
                for (int p = 0; p < j; p++) if (gidx == selg[p]) skip = true;
                if (skip) continue;
                float adj = sc + g_t5v[row * 640 + c] - lse;
                if (adj > bv || (adj == bv && gidx < bi)) { bv = adj; bi = gidx; }
            }
#pragma unroll
            for (int off = 16; off > 0; off >>= 1) {
                float ov = __shfl_xor_sync(full, bv, off);
                int   oi = __shfl_xor_sync(full, bi, off);
                if (ov > bv || (ov == bv && oi < bi)) { bv = ov; bi = oi; }
            }
            selg[j] = bi; selv[j] = bv;
        }
        if (lane == 0) {
#pragma unroll
            for (int j = 0; j < KBM; j++) {
                t_rv[warp * KBM + j] = selv[j];
                t_ri[warp * KBM + j] = selg[j];
            }
        }
    }
    __syncthreads();
    if (warp == 0) {
        float v  = (lane < 25) ? t_rv[lane] : NEGF;
        int   gi = (lane < 25) ? t_ri[lane] : 0x7fffffff;
        bool chosen = false;
        for (int j = 0; j < KBM; j++) {
            float cv = chosen ? NEGF : v;
            int ci = gi;
#pragma unroll
            for (int off = 16; off > 0; off >>= 1) {
                float ov = __shfl_xor_sync(full, cv, off);
                int   oi = __shfl_xor_sync(full, ci, off);
                if (ov > cv || (ov == cv && oi < ci)) { cv = ov; ci = oi; }
            }
            if (lane == 0) { t_fv[j] = cv; t_fi[j] = ci; }
            if (gi == ci) chosen = true;
        }
    }
    __syncthreads();
    if (tid < KBM) {
        int idx = t_fi[tid];
        int par = idx >> 12, tok = idx & 4095;
        int blank = (tok == 0);
        int p = b * KBM + par, mn = b * KBM + tid;
        t_par[tid] = par; t_tok[tid] = tok; t_blk2[tid] = blank;
        int pl = g_lens[cur][p];
        t_plen[tid] = pl;
        g_scores[nxt][mn] = t_fv[tid];
        g_lens[nxt][mn]   = pl + (blank ? 0 : 1);
        g_tokens[nxt][mn] = blank ? g_tokens[cur][p] : tok;
    }
    __syncthreads();
    // gather h/c (float4) and preds (int4 + scalar patch)
    for (int j = 0; j < KBM; j++) {
        int p = b * KBM + t_par[j], mn = b * KBM + j;
        bool blank = (t_blk2[j] != 0);
        const float4* hs = (const float4*)(blank ? &g_h[cur][p * HH] : &g_hnew[p * HH]);
        const float4* cs = (const float4*)(blank ? &g_c[cur][p * HH] : &g_cnew[p * HH]);
        float4* hd = (float4*)&g_h[nxt][mn * HH];
        float4* cd = (float4*)&g_c[nxt][mn * HH];
        if (tid < HH / 4) {
            hd[tid] = hs[tid];
            cd[tid] = cs[tid];
        }
        if (tid < TT / 4) {
            int4 v = ((const int4*)&g_preds[cur][p * TT])[tid];
            if (!blank) {
                int base = tid * 4;
                if (t_plen[j] - base >= 0 && t_plen[j] - base < 4) {
                    int w = t_plen[j] - base;
                    if (w == 0) v.x = t_tok[j];
                    else if (w == 1) v.y = t_tok[j];
                    else if (w == 2) v.z = t_tok[j];
                    else v.w = t_tok[j];
                }
            }
            ((int4*)&g_preds[nxt][mn * TT])[tid] = v;
        }
    }
}

// ----------------------------- finalize -------------------------------------
__device__ void finalize_stage(float* __restrict__ out) {
    int tid = threadIdx.x;
    __shared__ float s_norm[MM];
    __shared__ int   s_best[BB];
    if (tid < MM)
        s_norm[tid] = g_scores[0][tid] / ((float)g_lens[0][tid] + 1.0f);
    __syncthreads();
    if (tid < BB) {
        float bv = NEGF; int bj = 0;
        for (int j = 0; j < KBM; j++) {
            float v = s_norm[tid * KBM + j];
            if (v > bv) { bv = v; bj = j; }
        }
        s_best[tid] = bj;
        out[BB * TT + tid] = (float)g_lens[0][tid * KBM + bj];
    }
    if (tid < MM) out[BB * TT + BB + 1 + tid] = s_norm[tid];
    __syncthreads();
    if (tid == 0) {
        float acc = 0.0f;
        for (int b2 = 0; b2 < BB; b2++) {
            float bv = NEGF;
            for (int j = 0; j < KBM; j++) bv = fmaxf(bv, s_norm[b2 * KBM + j]);
            acc += expf(bv);
        }
        out[BB * TT + BB] = acc / (float)BB;
    }
    for (int b2 = 0; b2 < BB; b2++) {
        int m = b2 * KBM + s_best[b2];
        for (int i = tid; i < TT; i += 256)
            out[b2 * TT + i] = (float)g_preds[0][m * TT + i];
    }
}

// ----------------------------- persistent kernel ----------------------------
__global__ __launch_bounds__(256, 2) void persist(const float* __restrict__ E,
                                                  const float* __restrict__ Wpn,
                                                  const float* __restrict__ b_joint,
                                                  const float* __restrict__ Wout,
                                                  const float* __restrict__ bout,
                                                  float* __restrict__ out) {
    __shared__ Smem sm;
    unsigned int ph = 0;
    int blk = blockIdx.x;
    for (int t = 0; t < TT; t++) {
        int cur = t & 1;
        if (blk < 256) gates_stage(&sm, blk, cur, E);
        gbar(ph);
        if (blk < 128) pn_stage(&sm, blk, cur, Wpn);
        gbar(ph);
        joint_stage(b_joint, t, blk);
        gbar(ph);
        if (blk < 256) out_stage(&sm, blk, Wout);
        gbar(ph);
        stats_stage(blk, bout);
        gbar(ph);
        if (blk < BB) topk_stage(blk, cur);
        gbar(ph);
    }
    if (blk == 0) finalize_stage(out);
}

// ----------------------------- launch ---------------------------------------
extern "C" void kernel_launch(void* const* d_in, const int* in_sizes, int n_in,
                              void* d_out, int out_size) {
    const float* tn      = (const float*)d_in[0];
    const float* E       = (const float*)d_in[1];
    const float* W_ih    = (const float*)d_in[2];
    const float* W_hh    = (const float*)d_in[3];
    const float* b_lstm  = (const float*)d_in[4];
    const float* W_tn    = (const float*)d_in[5];
    const float* W_pn    = (const float*)d_in[6];
    const float* b_joint = (const float*)d_in[7];
    const float* W_out   = (const float*)d_in[8];
    const float* b_out   = (const float*)d_in[9];
    float* out = (float*)d_out;

    init_state<<<160, 256>>>(b_lstm);
    permute_w<<<dim3(64, 128), dim3(32, 8)>>>(W_ih, W_hh);
    tnproj_gemm<<<dim3(16, 16), 256>>>(tn, W_tn);
    persist<<<GRID_ALL, 256>>>(E, W_pn, b_joint, W_out, b_out, out);
}

// round 14
// speedup vs baseline: 1.3334x; 1.1879x over previous
#include <cuda_runtime.h>
#include <cuda_bf16.h>
#include <cstdint>
#include <cstddef>

// RNN-T beam search. B=8, T=128, H=1024, V=4096, K=5 (M = 40 hyps).
// Persistent kernel (2 CTAs/SM), cp.async double-buffered split-K GEMMs,
// packed fma.rn.f32x2 inner loops. R7 structure + threadfence barrier +
// vectorized topk gather.

#define HH   1024
#define VV   4096
#define BB   8
#define KBM  5
#define MM   40
#define TT   128
#define GRID_ALL 296
#define NEGF -3.0e38f

typedef unsigned long long u64;

// ----------------------------- device state --------------------------------
__device__ __align__(16) float g_tnproj[BB * TT * HH];
__device__ __align__(16) float g_WcatT[2048 * 4096];       // [k][n'] gate-permuted
__device__ __align__(16) float g_blstm_p[4096];            // permuted bias [4u+g]
__device__ __align__(16) float g_bufA[16 * MM * VV];       // gates/out partials
__device__ __align__(16) float g_bufB[32 * MM * HH];       // pn partials
__device__ __align__(16) float g_h[2][MM * HH];
__device__ __align__(16) float g_c[2][MM * HH];
__device__ __align__(16) float g_hnew[MM * HH];
__device__ __align__(16) float g_cnew[MM * HH];
__device__ __align__(16) float g_joint[MM * HH];
__device__ float g_rmax[MM * 128];
__device__ float g_rsum[MM * 128];
__device__ float g_t5v[MM * 640];
__device__ int   g_t5i[MM * 640];
__device__ float g_scores[2][MM];
__device__ int   g_tokens[2][MM];
__device__ int   g_lens[2][MM];
__device__ __align__(16) int g_preds[2][MM * TT];
__device__ unsigned int g_barcnt;

__device__ __forceinline__ float sigm(float x) { return 1.0f / (1.0f + expf(-x)); }

// ----------------------------- packed f32x2 ---------------------------------
__device__ __forceinline__ u64 pk2(float a) {
    u64 r;
    asm("mov.b64 %0, {%1, %1};" : "=l"(r) : "f"(a));
    return r;
}
__device__ __forceinline__ void fma2(u64& d, u64 a, u64 b) {
    asm("fma.rn.f32x2 %0, %1, %2, %0;" : "+l"(d) : "l"(a), "l"(b));
}

// ----------------------------- cp.async helpers -----------------------------
__device__ __forceinline__ void cpa16(void* s, const void* g) {
    uint32_t sa = (uint32_t)__cvta_generic_to_shared(s);
    asm volatile("cp.async.cg.shared.global [%0], [%1], 16;" :: "r"(sa), "l"(g));
}
#define CPA_COMMIT()  asm volatile("cp.async.commit_group;" ::: "memory")
#define CPA_WAIT(N)   asm volatile("cp.async.wait_group %0;" :: "n"(N) : "memory")

// ---------------------- grid barrier (monotonic counter) --------------------
// NOTE: fence + volatile poll. The red.release/ld.acquire poll variant was
// measured ~1us/barrier SLOWER (R10-R12) — do not "optimize" this again.
__device__ __forceinline__ void gbar(unsigned int& ph) {
    __syncthreads();
    ph++;
    if (threadIdx.x == 0) {
        __threadfence();
        atomicAdd(&g_barcnt, 1u);
        unsigned int target = ph * (unsigned int)GRID_ALL;
        while (*(volatile unsigned int*)&g_barcnt < target) __nanosleep(32);
        __threadfence();
    }
    __syncthreads();
}

// ----------------------------- init ----------------------------------------
__global__ void init_state(const float* __restrict__ b_lstm) {
    int idx = blockIdx.x * 256 + threadIdx.x;
    if (idx < MM * HH) { g_h[0][idx] = 0.0f; g_c[0][idx] = 0.0f; }
    if (idx < MM) {
        g_scores[0][idx] = (idx % KBM == 0) ? 0.0f : -1e9f;
        g_tokens[0][idx] = 0;
        g_lens[0][idx]   = 0;
    }
    if (idx < MM * TT) g_preds[0][idx] = 0;
    if (idx < 4096) g_blstm_p[idx] = b_lstm[(idx & 3) * 1024 + (idx >> 2)];
    if (idx == 0) g_barcnt = 0u;
}

// --------------------- weight transpose + gate permute ----------------------
__global__ void permute_w(const float* __restrict__ Wih,
                          const float* __restrict__ Whh) {
    __shared__ float tile[32][33];
    int x = threadIdx.x, y0 = threadIdx.y;
    int kt = blockIdx.x * 32, nt = blockIdx.y * 32;
#pragma unroll
    for (int yy = 0; yy < 32; yy += 8) {
        int np = nt + y0 + yy;
        int row = (np & 3) * 1024 + (np >> 2);
        int k = kt + x;
        float v = (k < 1024) ? Wih[(size_t)row * 1024 + k]
                             : Whh[(size_t)row * 1024 + k - 1024];
        tile[y0 + yy][x] = v;
    }
    __syncthreads();
#pragma unroll
    for (int yy = 0; yy < 32; yy += 8) {
        int k = kt + y0 + yy;
        int np = nt + x;
        g_WcatT[(size_t)k * 4096 + np] = tile[x][y0 + yy];
    }
}

// ----------------------------- tn_proj GEMM --------------------------------
__global__ __launch_bounds__(256) void tnproj_gemm(const float* __restrict__ A,
                                                   const float* __restrict__ Bm) {
    __shared__ float As[16][65];
    __shared__ float Bs[16][64];
    int tid = threadIdx.x;
    int tx = tid & 15, ty = tid >> 4;
    int m0 = blockIdx.y * 64, n0 = blockIdx.x * 64;
    float acc[4][4];
#pragma unroll
    for (int i = 0; i < 4; i++)
#pragma unroll
        for (int j = 0; j < 4; j++) acc[i][j] = 0.0f;
    for (int kk = 0; kk < 1024; kk += 16) {
        {
            int mm = tid >> 2;
            int kq = (tid & 3) * 4;
            float4 v = *(const float4*)&A[(size_t)(m0 + mm) * 1024 + kk + kq];
            As[kq + 0][mm] = v.x; As[kq + 1][mm] = v.y;
            As[kq + 2][mm] = v.z; As[kq + 3][mm] = v.w;
        }
#pragma unroll
        for (int r = 0; r < 4; r++) {
            int idx = tid + r * 256;
            int k = idx >> 6, n = idx & 63;
            Bs[k][n] = Bm[(size_t)(kk + k) * 1024 + n0 + n];
        }
        __syncthreads();
#pragma unroll
        for (int k = 0; k < 16; k++) {
            float a[4], b[4];
#pragma unroll
            for (int i = 0; i < 4; i++) a[i] = As[k][ty + 16 * i];
#pragma unroll
            for (int j = 0; j < 4; j++) b[j] = Bs[k][tx + 16 * j];
#pragma unroll
            for (int i = 0; i < 4; i++)
#pragma unroll
                for (int j = 0; j < 4; j++) acc[i][j] += a[i] * b[j];
        }
        __syncthreads();
    }
#pragma unroll
    for (int i = 0; i < 4; i++)
#pragma unroll
        for (int j = 0; j < 4; j++)
            g_tnproj[(size_t)(m0 + ty + 16 * i) * 1024 + n0 + tx + 16 * j] = acc[i][j];
}

// =========================== persistent stages ==============================
struct Smem {
    float As[2][MM][32];      // [m][k] chunk
    float Bs[2][32][256];     // [k][n] chunk
    int   tok[MM];
};

// FFMA2 inner product over one 32-k chunk; thread owns column pairs
// {nn2+64j, nn2+64j+1}, j=0..3, rows mg*5..mg*5+4.
__device__ __forceinline__ void mm_compute2(const float (*As)[32], const float (*Bs)[256],
                                            u64 acc[5][4], int nn2, int mg) {
#pragma unroll 4
    for (int kk = 0; kk < 32; kk++) {
        u64 b[4];
#pragma unroll
        for (int j = 0; j < 4; j++) b[j] = *(const u64*)&Bs[kk][nn2 + 64 * j];
#pragma unroll
        for (int i = 0; i < 5; i++) {
            u64 a2 = pk2(As[mg * 5 + i][kk]);
#pragma unroll
            for (int j = 0; j < 4; j++) fma2(acc[i][j], a2, b[j]);
        }
    }
}

// gates: 16 col-blocks(256) x 16 k-splits(128) = 256 CTAs, 4 chunks of 32.
__device__ void gates_stage(Smem* sm, int blk, int cur, const float* __restrict__ E) {
    int tid = threadIdx.x;
    int cb = blk & 15, sp = blk >> 4;
    int n0 = cb * 256, kb0 = sp * 128;
    if (tid < MM) sm->tok[tid] = g_tokens[cur][tid];
    __syncthreads();

    auto stage = [&](int c) {
        int kg = kb0 + c * 32;
        int buf = c & 1;
#pragma unroll
        for (int r = 0; r < 2; r++) {
            int idx = tid + r * 256;
            if (idx < 320) {
                int m = idx >> 3, q = (idx & 7) * 4;
                const float* src = (kg < 1024)
                    ? &E[(size_t)sm->tok[m] * HH + kg + q]
                    : &g_h[cur][m * HH + (kg - 1024) + q];
                cpa16(&sm->As[buf][m][q], src);
            }
        }
#pragma unroll
        for (int r = 0; r < 8; r++) {
            int idx = tid + r * 256;
            int kk = idx >> 6, nq = (idx & 63) * 4;
            cpa16(&sm->Bs[buf][kk][nq], &g_WcatT[(size_t)(kg + kk) * 4096 + n0 + nq]);
        }
        CPA_COMMIT();
    };

    u64 acc[5][4];
#pragma unroll
    for (int i = 0; i < 5; i++)
#pragma unroll
        for (int j = 0; j < 4; j++) acc[i][j] = 0ull;
    int nn2 = (tid & 31) * 2, mg = tid >> 5;

    stage(0);
    for (int c = 0; c < 4; c++) {
        if (c + 1 < 4) { stage(c + 1); CPA_WAIT(1); }
        else           { CPA_WAIT(0); }
        __syncthreads();
        mm_compute2(sm->As[c & 1], sm->Bs[c & 1], acc, nn2, mg);
        __syncthreads();
    }
    float* p = g_bufA + (size_t)sp * MM * VV;
#pragma unroll
    for (int i = 0; i < 5; i++)
#pragma unroll
        for (int j = 0; j < 4; j++)
            *(u64*)&p[(mg * 5 + i) * VV + n0 + 64 * j + nn2] = acc[i][j];
}

// pn: 4 col-blocks(256) x 32 k-splits(32) = 128 CTAs. LSTM-reduce prologue.
__device__ void pn_stage(Smem* sm, int blk, int cur, const float* __restrict__ Wpn) {
    int tid = threadIdx.x;
    int cb = blk & 3, s = blk >> 2;
    int n0 = cb * 256, kl = s * 32;

#pragma unroll
    for (int r = 0; r < 8; r++) {
        int idx = tid + r * 256;
        int kk = idx >> 6, nq = (idx & 63) * 4;
        cpa16(&sm->Bs[0][kk][nq], &Wpn[(size_t)(kl + kk) * HH + n0 + nq]);
    }
    CPA_COMMIT();

    // LSTM prologue: hnew for (m, u=kl..kl+31) -> As[0][m][kk]
#pragma unroll
    for (int r = 0; r < 5; r++) {
        int idx = tid + r * 256;
        int m = idx >> 5, kk = idx & 31;
        int u = kl + kk;
        float4 s4 = make_float4(0.f, 0.f, 0.f, 0.f);
#pragma unroll
        for (int sp2 = 0; sp2 < 16; sp2++) {
            float4 q = *(const float4*)&g_bufA[(size_t)sp2 * MM * VV + m * VV + 4 * u];
            s4.x += q.x; s4.y += q.y; s4.z += q.z; s4.w += q.w;
        }
        float4 bb = *(const float4*)&g_blstm_p[4 * u];
        float gi = s4.x + bb.x, gf = s4.y + bb.y, gg = s4.z + bb.z, go = s4.w + bb.w;
        float co = g_c[cur][m * HH + u];
        float cn = sigm(gf) * co + sigm(gi) * tanhf(gg);
        float hn = sigm(go) * tanhf(cn);
        sm->As[0][m][kk] = hn;
        if (cb == 0) { g_hnew[m * HH + u] = hn; g_cnew[m * HH + u] = cn; }
    }
    CPA_WAIT(0);
    __syncthreads();

    u64 acc[5][4];
#pragma unroll
    for (int i = 0; i < 5; i++)
#pragma unroll
        for (int j = 0; j < 4; j++) acc[i][j] = 0ull;
    int nn2 = (tid & 31) * 2, mg = tid >> 5;
    mm_compute2(sm->As[0], sm->Bs[0], acc, nn2, mg);
    __syncthreads();

    float* p = g_bufB + (size_t)s * MM * HH;
#pragma unroll
    for (int i = 0; i < 5; i++)
#pragma unroll
        for (int j = 0; j < 4; j++)
            *(u64*)&p[(mg * 5 + i) * HH + n0 + 64 * j + nn2] = acc[i][j];
}

// joint: all CTAs, reduce 32 pn partials + bias + tnproj -> tanh
__device__ void joint_stage(const float* __restrict__ b_joint, int t, int blk) {
    for (int e = blk * 256 + threadIdx.x; e < MM * HH; e += GRID_ALL * 256) {
        int m = e >> 10, j = e & 1023;
        float v = b_joint[j];
#pragma unroll
        for (int s = 0; s < 32; s++) v += g_bufB[(size_t)s * MM * HH + e];
        int b = m / KBM;
        v += g_tnproj[((size_t)b * TT + t) * HH + j];
        g_joint[e] = tanhf(v);
    }
}

// out: 16 col-blocks(256) x 16 k-splits(64) = 256 CTAs, 2 chunks of 32.
__device__ void out_stage(Smem* sm, int blk, const float* __restrict__ Wout) {
    int tid = threadIdx.x;
    int cb = blk & 15, sp = blk >> 4;
    int n0 = cb * 256, kb0 = sp * 64;

    auto stage = [&](int c) {
        int kg = kb0 + c * 32;
        int buf = c & 1;
#pragma unroll
        for (int r = 0; r < 2; r++) {
            int idx = tid + r * 256;
            if (idx < 320) {
                int m = idx >> 3, q = (idx & 7) * 4;
                cpa16(&sm->As[buf][m][q], &g_joint[m * HH + kg + q]);
            }
        }
#pragma unroll
        for (int r = 0; r < 8; r++) {
            int idx = tid + r * 256;
            int kk = idx >> 6, nq = (idx & 63) * 4;
            cpa16(&sm->Bs[buf][kk][nq], &Wout[(size_t)(kg + kk) * VV + n0 + nq]);
        }
        CPA_COMMIT();
    };

    u64 acc[5][4];
#pragma unroll
    for (int i = 0; i < 5; i++)
#pragma unroll
        for (int j = 0; j < 4; j++) acc[i][j] = 0ull;
    int nn2 = (tid & 31) * 2, mg = tid >> 5;

    stage(0);
    for (int c = 0; c < 2; c++) {
        if (c + 1 < 2) { stage(c + 1); CPA_WAIT(1); }
        else           { CPA_WAIT(0); }
        __syncthreads();
        mm_compute2(sm->As[c & 1], sm->Bs[c & 1], acc, nn2, mg);
        __syncthreads();
    }
    float* p = g_bufA + (size_t)sp * MM * VV;
#pragma unroll
    for (int i = 0; i < 5; i++)
#pragma unroll
        for (int j = 0; j < 4; j++)
            *(u64*)&p[(mg * 5 + i) * VV + n0 + 64 * j + nn2] = acc[i][j];
}

// stats: all CTAs. 5120 (row, 32-col slice) tasks.
__device__ void stats_stage(int blk, const float* __restrict__ bout) {
    int warp = threadIdx.x >> 5, lane = threadIdx.x & 31;
    unsigned full = 0xffffffffu;
    for (int tk = blk * 8 + warp; tk < MM * 128; tk += GRID_ALL * 8) {
        int row = tk >> 7, sl = tk & 127;
        int col = sl * 32 + lane;
        float v = bout[col];
#pragma unroll
        for (int sp = 0; sp < 16; sp++)
            v += g_bufA[(size_t)sp * MM * VV + (size_t)row * VV + col];
        float mx = v;
#pragma unroll
        for (int off = 16; off > 0; off >>= 1)
            mx = fmaxf(mx, __shfl_xor_sync(full, mx, off));
        float se = expf(v - mx);
#pragma unroll
        for (int off = 16; off > 0; off >>= 1)
            se += __shfl_xor_sync(full, se, off);
        bool chosen = false;
        for (int j = 0; j < KBM; j++) {
            float cv = chosen ? NEGF : v;
            int ci = col;
#pragma unroll
            for (int off = 16; off > 0; off >>= 1) {
                float ov = __shfl_xor_sync(full, cv, off);
                int   oi = __shfl_xor_sync(full, ci, off);
                if (ov > cv || (ov == cv && oi < ci)) { cv = ov; ci = oi; }
            }
            if (lane == 0) {
                g_t5v[row * 640 + sl * 5 + j] = cv;
                g_t5i[row * 640 + sl * 5 + j] = ci;
            }
            if (col == ci) chosen = true;
        }
        if (lane == 0) { g_rmax[row * 128 + sl] = mx; g_rsum[row * 128 + sl] = se; }
    }
}

// topk merge + state update: 8 CTAs (one per batch). Vectorized gathers.
__device__ void topk_stage(int b, int cur) {
    int tid = threadIdx.x;
    int nxt = cur ^ 1;
    int warp = tid >> 5, lane = tid & 31;
    unsigned full = 0xffffffffu;
    __shared__ float t_rv[25];
    __shared__ int   t_ri[25];
    __shared__ float t_fv[KBM];
    __shared__ int   t_fi[KBM];
    __shared__ int   t_par[KBM], t_tok[KBM], t_blk2[KBM], t_plen[KBM];

    if (warp < KBM) {
        int row = b * KBM + warp;
        float rm[4], rs[4];
#pragma unroll
        for (int q = 0; q < 4; q++) {
            rm[q] = g_rmax[row * 128 + lane * 4 + q];
            rs[q] = g_rsum[row * 128 + lane * 4 + q];
        }
        float M = fmaxf(fmaxf(rm[0], rm[1]), fmaxf(rm[2], rm[3]));
#pragma unroll
        for (int off = 16; off > 0; off >>= 1)
            M = fmaxf(M, __shfl_xor_sync(full, M, off));
        float S = 0.f;
#pragma unroll
        for (int q = 0; q < 4; q++) S += rs[q] * expf(rm[q] - M);
#pragma unroll
        for (int off = 16; off > 0; off >>= 1)
            S += __shfl_xor_sync(full, S, off);
        float lse = M + logf(S);
        float sc = g_scores[cur][row];
        int selg[KBM]; float selv[KBM];
        for (int j = 0; j < KBM; j++) {
            float bv = NEGF; int bi = 0x7fffffff;
            for (int q = 0; q < 20; q++) {
                int c = lane * 20 + q;
                int gidx = warp * 4096 + g_t5i[row * 640 + c];
                bool skip = false;
                for (int p = 0; p < j; p++) if (gidx == selg[p]) skip = true;
                if (skip) continue;
                float adj = sc + g_t5v[row * 640 + c] - lse;
                if (adj > bv || (adj == bv && gidx < bi)) { bv = adj; bi = gidx; }
            }
#pragma unroll
            for (int off = 16; off > 0; off >>= 1) {
                float ov = __shfl_xor_sync(full, bv, off);
                int   oi = __shfl_xor_sync(full, bi, off);
                if (ov > bv || (ov == bv && oi < bi)) { bv = ov; bi = oi; }
            }
            selg[j] = bi; selv[j] = bv;
        }
        if (lane == 0) {
#pragma unroll
            for (int j = 0; j < KBM; j++) {
                t_rv[warp * KBM + j] = selv[j];
                t_ri[warp * KBM + j] = selg[j];
            }
        }
    }
    __syncthreads();
    if (warp == 0) {
        float v  = (lane < 25) ? t_rv[lane] : NEGF;
        int   gi = (lane < 25) ? t_ri[lane] : 0x7fffffff;
        bool chosen = false;
        for (int j = 0; j < KBM; j++) {
            float cv = chosen ? NEGF : v;
            int ci = gi;
#pragma unroll
            for (int off = 16; off > 0; off >>= 1) {
                float ov = __shfl_xor_sync(full, cv, off);
                int   oi = __shfl_xor_sync(full, ci, off);
                if (ov > cv || (ov == cv && oi < ci)) { cv = ov; ci = oi; }
            }
            if (lane == 0) { t_fv[j] = cv; t_fi[j] = ci; }
            if (gi == ci) chosen = true;
        }
    }
    __syncthreads();
    if (tid < KBM) {
        int idx = t_fi[tid];
        int par = idx >> 12, tok = idx & 4095;
        int blank = (tok == 0);
        int p = b * KBM + par, mn = b * KBM + tid;
        t_par[tid] = par; t_tok[tid] = tok; t_blk2[tid] = blank;
        int pl = g_lens[cur][p];
        t_plen[tid] = pl;
        g_scores[nxt][mn] = t_fv[tid];
        g_lens[nxt][mn]   = pl + (blank ? 0 : 1);
        g_tokens[nxt][mn] = blank ? g_tokens[cur][p] : tok;
    }
    __syncthreads();
    // gather h/c (float4) and preds (int4 + scalar patch)
    for (int j = 0; j < KBM; j++) {
        int p = b * KBM + t_par[j], mn = b * KBM + j;
        bool blank = (t_blk2[j] != 0);
        const float4* hs = (const float4*)(blank ? &g_h[cur][p * HH] : &g_hnew[p * HH]);
        const float4* cs = (const float4*)(blank ? &g_c[cur][p * HH] : &g_cnew[p * HH]);
        float4* hd = (float4*)&g_h[nxt][mn * HH];
        float4* cd = (float4*)&g_c[nxt][mn * HH];
        if (tid < HH / 4) {
            hd[tid] = hs[tid];
            cd[tid] = cs[tid];
        }
        if (tid < TT / 4) {
            int4 v = ((const int4*)&g_preds[cur][p * TT])[tid];
            if (!blank) {
                int w = t_plen[j] - tid * 4;
                if (w >= 0 && w < 4) {
                    if (w == 0) v.x = t_tok[j];
                    else if (w == 1) v.y = t_tok[j];
                    else if (w == 2) v.z = t_tok[j];
                    else v.w = t_tok[j];
                }
            }
            ((int4*)&g_preds[nxt][mn * TT])[tid] = v;
        }
    }
}

// ----------------------------- finalize -------------------------------------
__device__ void finalize_stage(float* __restrict__ out) {
    int tid = threadIdx.x;
    __shared__ float s_norm[MM];
    __shared__ int   s_best[BB];
    if (tid < MM)
        s_norm[tid] = g_scores[0][tid] / ((float)g_lens[0][tid] + 1.0f);
    __syncthreads();
    if (tid < BB) {
        float bv = NEGF; int bj = 0;
        for (int j = 0; j < KBM; j++) {
            float v = s_norm[tid * KBM + j];
            if (v > bv) { bv = v; bj = j; }
        }
        s_best[tid] = bj;
        out[BB * TT + tid] = (float)g_lens[0][tid * KBM + bj];
    }
    if (tid < MM) out[BB * TT + BB + 1 + tid] = s_norm[tid];
    __syncthreads();
    if (tid == 0) {
        float acc = 0.0f;
        for (int b2 = 0; b2 < BB; b2++) {
            float bv = NEGF;
            for (int j = 0; j < KBM; j++) bv = fmaxf(bv, s_norm[b2 * KBM + j]);
            acc += expf(bv);
        }
        out[BB * TT + BB] = acc / (float)BB;
    }
    for (int b2 = 0; b2 < BB; b2++) {
        int m = b2 * KBM + s_best[b2];
        for (int i = tid; i < TT; i += 256)
            out[b2 * TT + i] = (float)g_preds[0][m * TT + i];
    }
}

// ----------------------------- persistent kernel ----------------------------
__global__ __launch_bounds__(256, 2) void persist(const float* __restrict__ E,
                                                  const float* __restrict__ Wpn,
                                                  const float* __restrict__ b_joint,
                                                  const float* __restrict__ Wout,
                                                  const float* __restrict__ bout,
                                                  float* __restrict__ out) {
    __shared__ Smem sm;
    unsigned int ph = 0;
    int blk = blockIdx.x;
    for (int t = 0; t < TT; t++) {
        int cur = t & 1;
        if (blk < 256) gates_stage(&sm, blk, cur, E);
        gbar(ph);
        if (blk < 128) pn_stage(&sm, blk, cur, Wpn);
        gbar(ph);
        joint_stage(b_joint, t, blk);
        gbar(ph);
        if (blk < 256) out_stage(&sm, blk, Wout);
        gbar(ph);
        stats_stage(blk, bout);
        gbar(ph);
        if (blk < BB) topk_stage(blk, cur);
        gbar(ph);
    }
    if (blk == 0) finalize_stage(out);
}

// ----------------------------- launch ---------------------------------------
extern "C" void kernel_launch(void* const* d_in, const int* in_sizes, int n_in,
                              void* d_out, int out_size) {
    const float* tn      = (const float*)d_in[0];
    const float* E       = (const float*)d_in[1];
    const float* W_ih    = (const float*)d_in[2];
    const float* W_hh    = (const float*)d_in[3];
    const float* b_lstm  = (const float*)d_in[4];
    const float* W_tn    = (const float*)d_in[5];
    const float* W_pn    = (const float*)d_in[6];
    const float* b_joint = (const float*)d_in[7];
    const float* W_out   = (const float*)d_in[8];
    const float* b_out   = (const float*)d_in[9];
    float* out = (float*)d_out;

    init_state<<<160, 256>>>(b_lstm);
    permute_w<<<dim3(64, 128), dim3(32, 8)>>>(W_ih, W_hh);
    tnproj_gemm<<<dim3(16, 16), 256>>>(tn, W_tn);
    persist<<<GRID_ALL, 256>>>(E, W_pn, b_joint, W_out, b_out, out);
}